// round 2
// baseline (speedup 1.0000x reference)
#include <cuda_runtime.h>
#include <cstdint>

#define N_NODES 100000
#define N_EDGES 600000

typedef unsigned long long ull;

// Scratch: per-node projections, [node][0..9] = h·W1^T, [node][10..19] = h·W2^T
__device__ float g_P[N_NODES * 20];
__device__ int g_shift;   // 0 if src/dst are int32, 1 if int64 (index via e<<shift)

__device__ __forceinline__ void ffma2(ull &acc, ull a, ull b) {
    asm("fma.rn.f32x2 %0, %1, %2, %0;" : "+l"(acc) : "l"(a), "l"(b));
}
__device__ __forceinline__ float pairsum(ull a) {
    unsigned lo, hi;
    asm("mov.b64 {%0,%1}, %2;" : "=r"(lo), "=r"(hi) : "l"(a));
    return __uint_as_float(lo) + __uint_as_float(hi);
}

// Detect whether src is int64 (odd 32-bit words all zero since indices < 2^17)
// or int32 (odd words are themselves random indices, ~never all zero).
__global__ void detect_kernel(const unsigned* __restrict__ s) {
    int tid = threadIdx.x;
    int bad = (s[2 * tid + 1] != 0u) ? 1 : 0;
    int any = __syncthreads_or(bad);
    if (tid == 0) g_shift = any ? 0 : 1;
}

// Kernel A: P[n][j] = sum_k h[n][k] * W_w[j%10][(j/10)*128 + k],  j in [0,20)
// One warp per node: lane = cg(2b) * 8 + r(3b); cg picks 5 of 20 outputs,
// r picks 16 of 128 k-values. Weights register-resident, amortized by grid-stride.
__global__ void __launch_bounds__(256) node_proj_kernel(
    const float* __restrict__ h, const float* __restrict__ W)
{
    const int l  = threadIdx.x & 31;
    const int cg = l >> 3;
    const int r  = l & 7;
    const int warp   = (blockIdx.x * blockDim.x + threadIdx.x) >> 5;
    const int nwarps = (gridDim.x * blockDim.x) >> 5;

    ull w[5][8];
#pragma unroll
    for (int i = 0; i < 5; i++) {
        int j    = cg * 5 + i;
        int row  = j % 10;
        int half = j / 10;
        const ulonglong2* wp = (const ulonglong2*)(W + row * 384 + half * 128 + r * 16);
#pragma unroll
        for (int q = 0; q < 4; q++) { ulonglong2 t = wp[q]; w[i][2*q] = t.x; w[i][2*q+1] = t.y; }
    }

    for (int n = warp; n < N_NODES; n += nwarps) {
        const ulonglong2* hp = (const ulonglong2*)(h + (size_t)n * 128 + r * 16);
        ull x[8];
#pragma unroll
        for (int q = 0; q < 4; q++) { ulonglong2 t = hp[q]; x[2*q] = t.x; x[2*q+1] = t.y; }
        ull acc[5] = {0ull, 0ull, 0ull, 0ull, 0ull};
#pragma unroll
        for (int i = 0; i < 5; i++)
#pragma unroll
            for (int q = 0; q < 8; q++)
                ffma2(acc[i], x[q], w[i][q]);
        float sc[5];
#pragma unroll
        for (int i = 0; i < 5; i++) sc[i] = pairsum(acc[i]);
#pragma unroll
        for (int m = 1; m <= 4; m <<= 1)
#pragma unroll
            for (int i = 0; i < 5; i++)
                sc[i] += __shfl_xor_sync(0xffffffffu, sc[i], m);
        if (r < 5) {
            float v = sc[0];
            if (r == 1) v = sc[1];
            else if (r == 2) v = sc[2];
            else if (r == 3) v = sc[3];
            else if (r == 4) v = sc[4];
            g_P[n * 20 + cg * 5 + r] = v;
        }
    }
}

// Kernel B: out[e][c] = edge_h[e]·W3[c] + P[src[e]][c] + P[dst[e]][10+c] + b[c]
// 16 lanes per edge (2 edges/warp): lane = g(1b)*16 + cg(1b)*8 + r(3b).
// cg picks 5 of 10 outputs, r picks 16 of 128 k. W3 register-resident.
__global__ void __launch_bounds__(256) edge_score_kernel(
    const float* __restrict__ eh, const float* __restrict__ W,
    const float* __restrict__ bvec, const int* __restrict__ src,
    const int* __restrict__ dst, float* __restrict__ out)
{
    const int l  = threadIdx.x & 31;
    const int g  = l >> 4;
    const int t  = l & 15;
    const int cg = t >> 3;
    const int r  = t & 7;
    const int warp   = (blockIdx.x * blockDim.x + threadIdx.x) >> 5;
    const int nwarps = (gridDim.x * blockDim.x) >> 5;
    const int shift  = g_shift;

    ull w[5][8];
#pragma unroll
    for (int i = 0; i < 5; i++) {
        int c = cg * 5 + i;
        const ulonglong2* wp = (const ulonglong2*)(W + c * 384 + 256 + r * 16);
#pragma unroll
        for (int q = 0; q < 4; q++) { ulonglong2 tt = wp[q]; w[i][2*q] = tt.x; w[i][2*q+1] = tt.y; }
    }
    const int myc = cg * 5 + r;                           // valid when r < 5
    const float bias = (r < 5) ? __ldg(bvec + myc) : 0.0f;

    for (int G = warp; G < N_EDGES / 2; G += nwarps) {
        const int e = G * 2 + g;
        float pv = 0.0f;
        if (r < 5) {
            int s = __ldg(src + ((size_t)e << shift));
            int d = __ldg(dst + ((size_t)e << shift));
            pv = g_P[s * 20 + myc] + g_P[d * 20 + 10 + myc] + bias;
        }
        const ulonglong2* xp = (const ulonglong2*)(eh + (size_t)e * 128 + r * 16);
        ull x[8];
#pragma unroll
        for (int q = 0; q < 4; q++) { ulonglong2 tt = xp[q]; x[2*q] = tt.x; x[2*q+1] = tt.y; }
        ull acc[5] = {0ull, 0ull, 0ull, 0ull, 0ull};
#pragma unroll
        for (int i = 0; i < 5; i++)
#pragma unroll
            for (int q = 0; q < 8; q++)
                ffma2(acc[i], x[q], w[i][q]);
        float sc[5];
#pragma unroll
        for (int i = 0; i < 5; i++) sc[i] = pairsum(acc[i]);
#pragma unroll
        for (int m = 1; m <= 4; m <<= 1)
#pragma unroll
            for (int i = 0; i < 5; i++)
                sc[i] += __shfl_xor_sync(0xffffffffu, sc[i], m);
        if (r < 5) {
            float v = sc[0];
            if (r == 1) v = sc[1];
            else if (r == 2) v = sc[2];
            else if (r == 3) v = sc[3];
            else if (r == 4) v = sc[4];
            out[(size_t)e * 10 + myc] = v + pv;
        }
    }
}

extern "C" void kernel_launch(void* const* d_in, const int* in_sizes, int n_in,
                              void* d_out, int out_size)
{
    const float* h    = (const float*)d_in[0];   // [100000, 128]
    const float* eh   = (const float*)d_in[1];   // [600000, 1, 128]
    const float* W_w  = (const float*)d_in[2];   // [10, 384]
    const float* W_b  = (const float*)d_in[3];   // [10]
    const int*   src  = (const int*)d_in[4];     // [600000] int32 or int64
    const int*   dst  = (const int*)d_in[5];     // [600000]
    float*       out  = (float*)d_out;           // [600000, 10]

    detect_kernel<<<1, 256>>>((const unsigned*)d_in[4]);
    node_proj_kernel<<<592, 256>>>(h, W_w);
    edge_score_kernel<<<1184, 256>>>(eh, W_w, W_b, src, dst, out);
}

// round 6
// speedup vs baseline: 1.1357x; 1.1357x over previous
#include <cuda_runtime.h>
#include <cstdint>

#define N_NODES 100000
#define N_EDGES 600000

typedef unsigned long long ull;

// Scratch: per-node projections, [node][0..9] = h·W1^T, [node][10..19] = h·W2^T
__device__ float g_P[N_NODES * 20];
__device__ int g_shift;   // 0 if src/dst are int32, 1 if int64 (index via e<<shift)

__device__ __forceinline__ void ffma2(ull &acc, ull a, ull b) {
    asm("fma.rn.f32x2 %0, %1, %2, %0;" : "+l"(acc) : "l"(a), "l"(b));
}
__device__ __forceinline__ float pairsum(ull a) {
    unsigned lo, hi;
    asm("mov.b64 {%0,%1}, %2;" : "=r"(lo), "=r"(hi) : "l"(a));
    return __uint_as_float(lo) + __uint_as_float(hi);
}

// Kernel A: P[n][j] = sum_k h[n][k] * W_w[j%10][(j/10)*128 + k],  j in [0,20)
// One warp per node: lane = cg(2b)*8 + r(3b); cg picks 5 of 20 outputs.
// K-INTERLEAVED: lane r owns float4 indices {q*8+r}, so each LDG.128
// instruction reads one contiguous 128B line per group, and all 4 cg groups
// hit the same addresses in the same instruction -> coalescer merges -> 1
// line per warp-instruction.
// Block 0 also performs the int32-vs-int64 index detection (odd 32-bit words
// of an int64 index array are all zero since indices < 2^17).
__global__ void __launch_bounds__(256) node_proj_kernel(
    const float* __restrict__ h, const float* __restrict__ W,
    const unsigned* __restrict__ srcu)
{
    if (blockIdx.x == 0 && threadIdx.x < 32) {
        unsigned v = srcu[2 * threadIdx.x + 1];
        unsigned any = __ballot_sync(0xffffffffu, v != 0u);
        if (threadIdx.x == 0) g_shift = any ? 0 : 1;
    }

    const int l  = threadIdx.x & 31;
    const int cg = l >> 3;
    const int r  = l & 7;
    const int warp   = (blockIdx.x * blockDim.x + threadIdx.x) >> 5;
    const int nwarps = (gridDim.x * blockDim.x) >> 5;

    // Weights for 5 outputs, k-slice = float4 indices q*8+r (q=0..3)
    ull w[5][8];
#pragma unroll
    for (int i = 0; i < 5; i++) {
        int j    = cg * 5 + i;
        int row  = j % 10;
        int half = j / 10;
        const ulonglong2* wp = (const ulonglong2*)(W + row * 384 + half * 128);
#pragma unroll
        for (int q = 0; q < 4; q++) {
            ulonglong2 t = wp[q * 8 + r];
            w[i][2 * q]     = t.x;
            w[i][2 * q + 1] = t.y;
        }
    }

    for (int n = warp; n < N_NODES; n += nwarps) {
        const ulonglong2* hp = (const ulonglong2*)(h + (size_t)n * 128);
        ull x[8];
#pragma unroll
        for (int q = 0; q < 4; q++) {
            ulonglong2 t = hp[q * 8 + r];
            x[2 * q]     = t.x;
            x[2 * q + 1] = t.y;
        }
        ull acc[5] = {0ull, 0ull, 0ull, 0ull, 0ull};
#pragma unroll
        for (int i = 0; i < 5; i++)
#pragma unroll
            for (int q = 0; q < 8; q++)
                ffma2(acc[i], x[q], w[i][q]);
        float sc[5];
#pragma unroll
        for (int i = 0; i < 5; i++) sc[i] = pairsum(acc[i]);
#pragma unroll
        for (int m = 1; m <= 4; m <<= 1)
#pragma unroll
            for (int i = 0; i < 5; i++)
                sc[i] += __shfl_xor_sync(0xffffffffu, sc[i], m);
        if (r < 5) {
            float v = sc[0];
            if (r == 1) v = sc[1];
            else if (r == 2) v = sc[2];
            else if (r == 3) v = sc[3];
            else if (r == 4) v = sc[4];
            g_P[n * 20 + cg * 5 + r] = v;
        }
    }
}

// Kernel B: out[e][c] = edge_h[e]·W3[c] + P[src[e]][c] + P[dst[e]][10+c] + b[c]
// 16 lanes per edge (2 edges/warp): lane = g(1b)*16 + cg(1b)*8 + r(3b).
// Same k-interleave: per LDG.128 instruction each 8-lane group reads one
// contiguous 128B line; cg=0 and cg=1 read identical addresses within the
// same instruction -> merged by the coalescer (no duplicate traffic).
__global__ void __launch_bounds__(256) edge_score_kernel(
    const float* __restrict__ eh, const float* __restrict__ W,
    const float* __restrict__ bvec, const int* __restrict__ src,
    const int* __restrict__ dst, float* __restrict__ out)
{
    const int l  = threadIdx.x & 31;
    const int g  = l >> 4;
    const int t  = l & 15;
    const int cg = t >> 3;
    const int r  = t & 7;
    const int warp   = (blockIdx.x * blockDim.x + threadIdx.x) >> 5;
    const int nwarps = (gridDim.x * blockDim.x) >> 5;
    const int shift  = g_shift;

    ull w[5][8];
#pragma unroll
    for (int i = 0; i < 5; i++) {
        int c = cg * 5 + i;
        const ulonglong2* wp = (const ulonglong2*)(W + c * 384 + 256);
#pragma unroll
        for (int q = 0; q < 4; q++) {
            ulonglong2 tt = wp[q * 8 + r];
            w[i][2 * q]     = tt.x;
            w[i][2 * q + 1] = tt.y;
        }
    }
    const int myc  = cg * 5 + r;                          // valid when r < 5
    const float bias = (r < 5) ? __ldg(bvec + myc) : 0.0f;

    for (int G = warp; G < N_EDGES / 2; G += nwarps) {
        const int e = G * 2 + g;
        // L2-resident random gathers issued first to overlap with streaming
        float pv = 0.0f;
        if (r < 5) {
            int s = __ldg(src + ((size_t)e << shift));
            int d = __ldg(dst + ((size_t)e << shift));
            pv = g_P[s * 20 + myc] + g_P[d * 20 + 10 + myc] + bias;
        }
        const ulonglong2* xp = (const ulonglong2*)(eh + (size_t)e * 128);
        ull x[8];
#pragma unroll
        for (int q = 0; q < 4; q++) {
            ulonglong2 tt = xp[q * 8 + r];
            x[2 * q]     = tt.x;
            x[2 * q + 1] = tt.y;
        }
        ull acc[5] = {0ull, 0ull, 0ull, 0ull, 0ull};
#pragma unroll
        for (int i = 0; i < 5; i++)
#pragma unroll
            for (int q = 0; q < 8; q++)
                ffma2(acc[i], x[q], w[i][q]);
        float sc[5];
#pragma unroll
        for (int i = 0; i < 5; i++) sc[i] = pairsum(acc[i]);
#pragma unroll
        for (int m = 1; m <= 4; m <<= 1)
#pragma unroll
            for (int i = 0; i < 5; i++)
                sc[i] += __shfl_xor_sync(0xffffffffu, sc[i], m);
        if (r < 5) {
            float v = sc[0];
            if (r == 1) v = sc[1];
            else if (r == 2) v = sc[2];
            else if (r == 3) v = sc[3];
            else if (r == 4) v = sc[4];
            out[(size_t)e * 10 + myc] = v + pv;
        }
    }
}

extern "C" void kernel_launch(void* const* d_in, const int* in_sizes, int n_in,
                              void* d_out, int out_size)
{
    const float* h    = (const float*)d_in[0];   // [100000, 128]
    const float* eh   = (const float*)d_in[1];   // [600000, 1, 128]
    const float* W_w  = (const float*)d_in[2];   // [10, 384]
    const float* W_b  = (const float*)d_in[3];   // [10]
    const int*   src  = (const int*)d_in[4];     // [600000] int32 or int64
    const int*   dst  = (const int*)d_in[5];     // [600000]
    float*       out  = (float*)d_out;           // [600000, 10]

    node_proj_kernel<<<592, 256>>>(h, W_w, (const unsigned*)d_in[4]);
    edge_score_kernel<<<1184, 256>>>(eh, W_w, W_b, src, dst, out);
}